// round 1
// baseline (speedup 1.0000x reference)
#include <cuda_runtime.h>
#include <math.h>

// Problem constants
#define BB 2
#define NN 4096
#define DD 256
#define NH 8
#define HD 32
#define GRID_H 64
#define GRID_W 64

// Scratch (allocation-free rule: __device__ globals)
__device__ float g_x2f[BB * NN * DD];
__device__ float g_q[BB * NN * DD];
__device__ float g_k[BB * NN * DD];
__device__ float g_v[BB * NN * DD];
__device__ float g_att[BB * NN * DD];

// ---------------------------------------------------------------------------
// Kernel 1: neighborhood fuse. One warp per (b, n). 10-way local attention
// (center + 3x3 window incl. center again), D=256 split 8 floats per lane.
// ---------------------------------------------------------------------------
__global__ __launch_bounds__(256) void neigh_fuse_kernel(const float* __restrict__ x2,
                                                         float* __restrict__ out) {
    int warp = (blockIdx.x * blockDim.x + threadIdx.x) >> 5;
    int lane = threadIdx.x & 31;
    if (warp >= BB * NN) return;
    int b = warp >> 12;          // / 4096
    int n = warp & (NN - 1);
    int row = n >> 6, col = n & 63;
    const float* xb = x2 + (size_t)b * NN * DD;

    int idx[10];
    bool valid[10];
    idx[0] = n; valid[0] = true;
    {
        int k = 1;
        #pragma unroll
        for (int di = -1; di <= 1; di++) {
            #pragma unroll
            for (int dj = -1; dj <= 1; dj++) {
                int r = row + di, c = col + dj;
                bool v = (r >= 0) && (r < GRID_H) && (c >= 0) && (c < GRID_W);
                valid[k] = v;
                idx[k] = v ? (r * GRID_W + c) : 0;
                k++;
            }
        }
    }

    float cen[8];
    const float* cp = xb + (size_t)n * DD;
    #pragma unroll
    for (int i = 0; i < 8; i++) cen[i] = cp[lane + 32 * i];

    float vreg[10][8];
    float score[10];
    #pragma unroll
    for (int kk = 0; kk < 10; kk++) {
        const float* p = xb + (size_t)idx[kk] * DD;
        float s = 0.f;
        #pragma unroll
        for (int i = 0; i < 8; i++) {
            float v = p[lane + 32 * i];
            vreg[kk][i] = v;
            s += cen[i] * v;
        }
        #pragma unroll
        for (int off = 16; off > 0; off >>= 1)
            s += __shfl_xor_sync(0xffffffffu, s, off);
        score[kk] = valid[kk] ? (s * (1.0f / 16.0f)) : -3.0e38f;  // /sqrt(256)
    }

    float m = score[0];
    #pragma unroll
    for (int kk = 1; kk < 10; kk++) m = fmaxf(m, score[kk]);
    float w[10];
    float l = 0.f;
    #pragma unroll
    for (int kk = 0; kk < 10; kk++) {
        float e = valid[kk] ? __expf(score[kk] - m) : 0.f;
        w[kk] = e;
        l += e;
    }
    float inv = 1.0f / l;

    float* o = out + (size_t)(b * NN + n) * DD;
    #pragma unroll
    for (int i = 0; i < 8; i++) {
        float a = 0.f;
        #pragma unroll
        for (int kk = 0; kk < 10; kk++) a += w[kk] * vreg[kk][i];
        o[lane + 32 * i] = a * inv;
    }
}

// ---------------------------------------------------------------------------
// Kernel 2: C[m][j] = sum_d A[m][d] * W[j][d] + bias[j]   (x @ W^T + b)
// M=8192 rows. 64x64 block tile, 256 threads, 4x4 micro tile, k-chunk 32.
// Column mapping j = tx + 16*jj keeps smem reads conflict-free.
// ---------------------------------------------------------------------------
__global__ __launch_bounds__(256) void gemm_nt_bias(const float* __restrict__ A,
                                                    const float* __restrict__ W,
                                                    const float* __restrict__ bias,
                                                    float* __restrict__ C) {
    __shared__ float As[64][33];
    __shared__ float Ws[64][33];
    int tid = threadIdx.x;
    int ty = tid >> 4, tx = tid & 15;
    int m0 = blockIdx.x * 64, j0 = blockIdx.y * 64;

    float acc[4][4];
    #pragma unroll
    for (int i = 0; i < 4; i++)
        #pragma unroll
        for (int j = 0; j < 4; j++) acc[i][j] = 0.f;

    for (int k0 = 0; k0 < DD; k0 += 32) {
        #pragma unroll
        for (int t = 0; t < 8; t++) {
            int e = tid + t * 256;
            int r = e >> 5, kk = e & 31;
            As[r][kk] = A[(size_t)(m0 + r) * DD + k0 + kk];
            Ws[r][kk] = W[(size_t)(j0 + r) * DD + k0 + kk];
        }
        __syncthreads();
        #pragma unroll
        for (int kk = 0; kk < 32; kk++) {
            float a[4], w[4];
            #pragma unroll
            for (int i = 0; i < 4; i++) a[i] = As[ty * 4 + i][kk];
            #pragma unroll
            for (int j = 0; j < 4; j++) w[j] = Ws[tx + 16 * j][kk];
            #pragma unroll
            for (int i = 0; i < 4; i++)
                #pragma unroll
                for (int j = 0; j < 4; j++) acc[i][j] += a[i] * w[j];
        }
        __syncthreads();
    }

    #pragma unroll
    for (int i = 0; i < 4; i++) {
        int m = m0 + ty * 4 + i;
        #pragma unroll
        for (int j = 0; j < 4; j++) {
            int jj = j0 + tx + 16 * j;
            C[(size_t)m * DD + jj] = acc[i][j] + bias[jj];
        }
    }
}

// ---------------------------------------------------------------------------
// Kernel 3: flash attention fp32. Block = 64 q-rows of one (b, h).
// K tiles of 64 rows; online softmax; P staged through smem.
// Thread (ty, tx): S rows ty*4+i, S cols tx+16*j; O cols tx*2, tx*2+1.
// ---------------------------------------------------------------------------
__global__ __launch_bounds__(256) void flash_attn_kernel(const float* __restrict__ Q,
                                                         const float* __restrict__ K,
                                                         const float* __restrict__ V,
                                                         float* __restrict__ O) {
    __shared__ float Qs[64][36];   // padded for float4 + bank spread
    __shared__ float Ks[64][36];
    __shared__ float Vs[64][34];
    __shared__ float Ps[64][68];

    int bh = blockIdx.y;
    int b = bh >> 3, h = bh & 7;
    int q0 = blockIdx.x * 64;
    const size_t base = (size_t)b * NN * DD + (size_t)h * HD;
    const float* Qp = Q + base;
    const float* Kp = K + base;
    const float* Vp = V + base;

    int tid = threadIdx.x;
    int ty = tid >> 4, tx = tid & 15;
    const float scale = 0.17677669529663688f;  // 1/sqrt(32)

    // load + pre-scale Q tile (64x32)
    #pragma unroll
    for (int t = 0; t < 8; t++) {
        int e = tid + t * 256;
        int r = e >> 5, d = e & 31;
        Qs[r][d] = Qp[(size_t)(q0 + r) * DD + d] * scale;
    }

    float m_run[4], l_run[4], acc[4][2];
    #pragma unroll
    for (int i = 0; i < 4; i++) {
        m_run[i] = -3.0e38f;
        l_run[i] = 0.f;
        acc[i][0] = 0.f;
        acc[i][1] = 0.f;
    }
    __syncthreads();

    for (int kt = 0; kt < NN / 64; kt++) {
        int k0 = kt * 64;
        #pragma unroll
        for (int t = 0; t < 8; t++) {
            int e = tid + t * 256;
            int r = e >> 5, d = e & 31;
            Ks[r][d] = Kp[(size_t)(k0 + r) * DD + d];
            Vs[r][d] = Vp[(size_t)(k0 + r) * DD + d];
        }
        __syncthreads();

        // S = Q K^T (4x4 micro, float4 over d)
        float s[4][4];
        #pragma unroll
        for (int i = 0; i < 4; i++)
            #pragma unroll
            for (int j = 0; j < 4; j++) s[i][j] = 0.f;
        #pragma unroll
        for (int d4 = 0; d4 < 8; d4++) {
            float4 a[4], kq[4];
            #pragma unroll
            for (int i = 0; i < 4; i++)
                a[i] = *(const float4*)&Qs[ty * 4 + i][d4 * 4];
            #pragma unroll
            for (int j = 0; j < 4; j++)
                kq[j] = *(const float4*)&Ks[tx + 16 * j][d4 * 4];
            #pragma unroll
            for (int i = 0; i < 4; i++)
                #pragma unroll
                for (int j = 0; j < 4; j++) {
                    s[i][j] += a[i].x * kq[j].x;
                    s[i][j] += a[i].y * kq[j].y;
                    s[i][j] += a[i].z * kq[j].z;
                    s[i][j] += a[i].w * kq[j].w;
                }
        }

        // Online softmax per q-row (redundant across the 16 tx lanes; consistent
        // because the butterfly reduces give all lanes the same value).
        #pragma unroll
        for (int i = 0; i < 4; i++) {
            float mt = fmaxf(fmaxf(s[i][0], s[i][1]), fmaxf(s[i][2], s[i][3]));
            #pragma unroll
            for (int off = 8; off > 0; off >>= 1)
                mt = fmaxf(mt, __shfl_xor_sync(0xffffffffu, mt, off));
            float m_new = fmaxf(m_run[i], mt);
            float al = __expf(m_run[i] - m_new);
            float rs = 0.f;
            #pragma unroll
            for (int j = 0; j < 4; j++) {
                float pv = __expf(s[i][j] - m_new);
                Ps[ty * 4 + i][tx + 16 * j] = pv;
                rs += pv;
            }
            #pragma unroll
            for (int off = 8; off > 0; off >>= 1)
                rs += __shfl_xor_sync(0xffffffffu, rs, off);
            l_run[i] = l_run[i] * al + rs;
            acc[i][0] *= al;
            acc[i][1] *= al;
            m_run[i] = m_new;
        }
        __syncthreads();

        // O += P @ V   (float4 P reads, float2 V reads)
        #pragma unroll 4
        for (int k4 = 0; k4 < 16; k4++) {
            float p[4][4];
            #pragma unroll
            for (int i = 0; i < 4; i++) {
                float4 t = *(const float4*)&Ps[ty * 4 + i][k4 * 4];
                p[i][0] = t.x; p[i][1] = t.y; p[i][2] = t.z; p[i][3] = t.w;
            }
            #pragma unroll
            for (int kk = 0; kk < 4; kk++) {
                float2 v = *(const float2*)&Vs[k4 * 4 + kk][tx * 2];
                #pragma unroll
                for (int i = 0; i < 4; i++) {
                    acc[i][0] += p[i][kk] * v.x;
                    acc[i][1] += p[i][kk] * v.y;
                }
            }
        }
        __syncthreads();
    }

    float* Op = O + base;
    #pragma unroll
    for (int i = 0; i < 4; i++) {
        float inv = 1.0f / l_run[i];
        size_t r = (size_t)(q0 + ty * 4 + i) * DD;
        Op[r + tx * 2]     = acc[i][0] * inv;
        Op[r + tx * 2 + 1] = acc[i][1] * inv;
    }
}

// ---------------------------------------------------------------------------
// Launch
// ---------------------------------------------------------------------------
extern "C" void kernel_launch(void* const* d_in, const int* in_sizes, int n_in,
                              void* d_out, int out_size) {
    const float* x1 = (const float*)d_in[0];
    const float* x2 = (const float*)d_in[1];
    const float* Wq = (const float*)d_in[2];
    const float* Wk = (const float*)d_in[3];
    const float* Wv = (const float*)d_in[4];
    const float* Wo = (const float*)d_in[5];
    const float* bq = (const float*)d_in[6];
    const float* bk = (const float*)d_in[7];
    const float* bv = (const float*)d_in[8];
    const float* bo = (const float*)d_in[9];
    float* out = (float*)d_out;

    float *x2f, *q, *k, *v, *att;
    cudaGetSymbolAddress((void**)&x2f, g_x2f);
    cudaGetSymbolAddress((void**)&q, g_q);
    cudaGetSymbolAddress((void**)&k, g_k);
    cudaGetSymbolAddress((void**)&v, g_v);
    cudaGetSymbolAddress((void**)&att, g_att);

    // 1. neighborhood fuse: 8192 warps
    neigh_fuse_kernel<<<BB * NN / 8, 256>>>(x2, x2f);

    // 2. Q/K/V projections
    dim3 ggrid(BB * NN / 64, DD / 64);
    gemm_nt_bias<<<ggrid, 256>>>(x1, Wq, bq, q);
    gemm_nt_bias<<<ggrid, 256>>>(x2f, Wk, bk, k);
    gemm_nt_bias<<<ggrid, 256>>>(x2f, Wv, bv, v);

    // 3. attention: 64 q-tiles x (B*H = 16)
    dim3 agrid(NN / 64, BB * NH);
    flash_attn_kernel<<<agrid, 256>>>(q, k, v, att);

    // 4. output projection -> d_out
    gemm_nt_bias<<<ggrid, 256>>>(att, Wo, bo, out);
}

// round 12
// speedup vs baseline: 2.4074x; 2.4074x over previous
#include <cuda_runtime.h>
#include <cstdint>
#include <math.h>

// Problem constants
#define BB 2
#define NN 4096
#define DD 256
#define NH 8
#define HD 32
#define GRID_H 64
#define GRID_W 64

// Scratch (allocation-free rule: __device__ globals)
__device__ float g_x2f[BB * NN * DD];
__device__ float g_q[BB * NN * DD];
__device__ float g_k[BB * NN * DD];
__device__ float g_v[BB * NN * DD];
__device__ float g_att[BB * NN * DD];

// ===========================================================================
// Helpers
// ===========================================================================
__device__ __forceinline__ uint32_t smem_u32(const void* p) {
    uint32_t a;
    asm("{ .reg .u64 t; cvta.to.shared.u64 t, %1; cvt.u32.u64 %0, t; }" : "=r"(a) : "l"(p));
    return a;
}

#define CP_ASYNC16(dst, src) \
    asm volatile("cp.async.cg.shared.global [%0], [%1], 16;" :: "r"(dst), "l"(src))
#define CP_COMMIT() asm volatile("cp.async.commit_group;" ::: "memory")
#define CP_WAIT1()  asm volatile("cp.async.wait_group 1;"  ::: "memory")

__device__ __forceinline__ uint32_t f2tf32(float v) {
    uint32_t r;
    asm("cvt.rna.tf32.f32 %0, %1;" : "=r"(r) : "f"(v));
    return r;
}

// m16n8k8 tf32 MMA, D accumulates in place (base-ISA, sm_80+, tensor pipe)
__device__ __forceinline__ void mma816(float* d, const uint32_t* a, uint32_t b0, uint32_t b1) {
    asm volatile("mma.sync.aligned.m16n8k8.row.col.f32.tf32.tf32.f32 "
                 "{%0,%1,%2,%3}, {%4,%5,%6,%7}, {%8,%9}, {%0,%1,%2,%3};"
                 : "+f"(d[0]), "+f"(d[1]), "+f"(d[2]), "+f"(d[3])
                 : "r"(a[0]), "r"(a[1]), "r"(a[2]), "r"(a[3]), "r"(b0), "r"(b1));
}

__device__ __forceinline__ uint32_t lds32(uint32_t addr) {
    uint32_t r;
    asm volatile("ld.shared.b32 %0, [%1];" : "=r"(r) : "r"(addr));
    return r;
}
__device__ __forceinline__ void sts64(uint32_t addr, uint32_t x, uint32_t y) {
    asm volatile("st.shared.v2.b32 [%0], {%1,%2};" :: "r"(addr), "r"(x), "r"(y) : "memory");
}

// SMEM layout (element = float). Pads chosen for conflict-free quad patterns:
//  K lds banks = 4*gid+tg (stride 36), V lds banks = 8*tg+gid (stride 40),
//  P lds banks = 4*gid+tg (stride 68).
#define KSTR 36
#define VSTR 40
#define PSTR 68
#define KS_OFF(buf)  ((buf) * (64 * KSTR))
#define VS_OFF(buf)  (2 * 64 * KSTR + (buf) * (64 * VSTR))
#define PS_OFF       (2 * 64 * KSTR + 2 * 64 * VSTR)
#define SMEM_FLOATS  (PS_OFF + 128 * PSTR)
#define SMEM_BYTES   (SMEM_FLOATS * 4)

// ---------------------------------------------------------------------------
// Kernel 1: neighborhood fuse (one warp per (b,n))
// ---------------------------------------------------------------------------
__global__ __launch_bounds__(256) void neigh_fuse_kernel(const float* __restrict__ x2,
                                                         float* __restrict__ out) {
    int warp = (blockIdx.x * blockDim.x + threadIdx.x) >> 5;
    int lane = threadIdx.x & 31;
    if (warp >= BB * NN) return;
    int b = warp >> 12;
    int n = warp & (NN - 1);
    int row = n >> 6, col = n & 63;
    const float* xb = x2 + (size_t)b * NN * DD;

    int idx[10];
    bool valid[10];
    idx[0] = n; valid[0] = true;
    {
        int k = 1;
        #pragma unroll
        for (int di = -1; di <= 1; di++)
            #pragma unroll
            for (int dj = -1; dj <= 1; dj++) {
                int r = row + di, c = col + dj;
                bool v = (r >= 0) && (r < GRID_H) && (c >= 0) && (c < GRID_W);
                valid[k] = v;
                idx[k] = v ? (r * GRID_W + c) : 0;
                k++;
            }
    }

    float cen[8];
    const float* cp = xb + (size_t)n * DD;
    #pragma unroll
    for (int i = 0; i < 8; i++) cen[i] = cp[lane + 32 * i];

    float vreg[10][8];
    float score[10];
    #pragma unroll
    for (int kk = 0; kk < 10; kk++) {
        const float* p = xb + (size_t)idx[kk] * DD;
        float s = 0.f;
        #pragma unroll
        for (int i = 0; i < 8; i++) {
            float v = p[lane + 32 * i];
            vreg[kk][i] = v;
            s += cen[i] * v;
        }
        #pragma unroll
        for (int off = 16; off > 0; off >>= 1)
            s += __shfl_xor_sync(0xffffffffu, s, off);
        score[kk] = valid[kk] ? (s * (1.0f / 16.0f)) : -3.0e38f;
    }

    float m = score[0];
    #pragma unroll
    for (int kk = 1; kk < 10; kk++) m = fmaxf(m, score[kk]);
    float w[10];
    float l = 0.f;
    #pragma unroll
    for (int kk = 0; kk < 10; kk++) {
        float e = valid[kk] ? __expf(score[kk] - m) : 0.f;
        w[kk] = e;
        l += e;
    }
    float inv = 1.0f / l;

    float* o = out + (size_t)(b * NN + n) * DD;
    #pragma unroll
    for (int i = 0; i < 8; i++) {
        float a = 0.f;
        #pragma unroll
        for (int kk = 0; kk < 10; kk++) a += w[kk] * vreg[kk][i];
        o[lane + 32 * i] = a * inv;
    }
}

// ---------------------------------------------------------------------------
// Kernel 2: C = A @ W^T + bias (fp32, 64x64 tile)
// ---------------------------------------------------------------------------
__global__ __launch_bounds__(256) void gemm_nt_bias(const float* __restrict__ A,
                                                    const float* __restrict__ W,
                                                    const float* __restrict__ bias,
                                                    float* __restrict__ C) {
    __shared__ float As[64][33];
    __shared__ float Ws[64][33];
    int tid = threadIdx.x;
    int ty = tid >> 4, tx = tid & 15;
    int m0 = blockIdx.x * 64, j0 = blockIdx.y * 64;

    float acc[4][4];
    #pragma unroll
    for (int i = 0; i < 4; i++)
        #pragma unroll
        for (int j = 0; j < 4; j++) acc[i][j] = 0.f;

    for (int k0 = 0; k0 < DD; k0 += 32) {
        #pragma unroll
        for (int t = 0; t < 8; t++) {
            int e = tid + t * 256;
            int r = e >> 5, kk = e & 31;
            As[r][kk] = A[(size_t)(m0 + r) * DD + k0 + kk];
            Ws[r][kk] = W[(size_t)(j0 + r) * DD + k0 + kk];
        }
        __syncthreads();
        #pragma unroll
        for (int kk = 0; kk < 32; kk++) {
            float a[4], w[4];
            #pragma unroll
            for (int i = 0; i < 4; i++) a[i] = As[ty * 4 + i][kk];
            #pragma unroll
            for (int j = 0; j < 4; j++) w[j] = Ws[tx + 16 * j][kk];
            #pragma unroll
            for (int i = 0; i < 4; i++)
                #pragma unroll
                for (int j = 0; j < 4; j++) acc[i][j] += a[i] * w[j];
        }
        __syncthreads();
    }

    #pragma unroll
    for (int i = 0; i < 4; i++) {
        int m = m0 + ty * 4 + i;
        #pragma unroll
        for (int j = 0; j < 4; j++) {
            int jj = j0 + tx + 16 * j;
            C[(size_t)m * DD + jj] = acc[i][j] + bias[jj];
        }
    }
}

// ---------------------------------------------------------------------------
// Kernel 3: flash attention via mma.sync tf32 (base-ISA tensor path).
// CTA = 128 q-rows of one (b,h), 8 warps, warp = 16 q-rows.
// K-tile = 64 keys, cp.async double-buffered.
// Thread roles within warp: gid = lane/4 (row), tg = lane%4 (col group).
// Warp w owns q-rows [16w,16w+16): fragment rows gid and gid+8.
// ---------------------------------------------------------------------------
__global__ __launch_bounds__(256, 2) void flash_mma_kernel(const float* __restrict__ Q,
                                                           const float* __restrict__ K,
                                                           const float* __restrict__ V,
                                                           float* __restrict__ O) {
    extern __shared__ float smf[];
    uint32_t sb = smem_u32(smf);
    int tid = threadIdx.x;
    int w = tid >> 5, lane = tid & 31;
    int gid = lane >> 2, tg = lane & 3;

    int bh = blockIdx.y;
    int b = bh >> 3, h = bh & 7;
    int q0 = blockIdx.x * 128;
    const size_t base = (size_t)b * NN * DD + (size_t)h * HD;
    const float* Qp = Q + base;
    const float* Kp = K + base;
    const float* Vp = V + base;

    // --- Q fragments (loaded once, tf32-rounded, pre-scaled) ---
    const float scale = 0.17677669529663688f;  // 1/sqrt(32)
    uint32_t qa[4][4];
    {
        const float* r0p = Qp + (size_t)(q0 + w * 16 + gid) * DD;
        const float* r1p = r0p + (size_t)8 * DD;
        #pragma unroll
        for (int ks = 0; ks < 4; ks++) {
            int c0 = ks * 8 + tg;
            qa[ks][0] = f2tf32(r0p[c0] * scale);
            qa[ks][1] = f2tf32(r1p[c0] * scale);
            qa[ks][2] = f2tf32(r0p[c0 + 4] * scale);
            qa[ks][3] = f2tf32(r1p[c0 + 4] * scale);
        }
    }

    // --- prologue: async-load K/V tiles 0,1 (64 rows x 32 floats each) ---
    #pragma unroll
    for (int pp = 0; pp < 2; pp++) {
        int k0 = pp * 64;
        #pragma unroll
        for (int i = 0; i < 2; i++) {
            int e = tid + i * 256;
            int row = e >> 3, ch = e & 7;
            CP_ASYNC16(sb + (KS_OFF(pp) + row * KSTR + ch * 4) * 4,
                       Kp + (size_t)(k0 + row) * DD + ch * 4);
            CP_ASYNC16(sb + (VS_OFF(pp) + row * VSTR + ch * 4) * 4,
                       Vp + (size_t)(k0 + row) * DD + ch * 4);
        }
        CP_COMMIT();
    }

    float m0 = -3.0e38f, m1 = -3.0e38f, l0 = 0.f, l1 = 0.f;
    float acc[4][4];
    #pragma unroll
    for (int nt = 0; nt < 4; nt++)
        #pragma unroll
        for (int t = 0; t < 4; t++) acc[nt][t] = 0.f;

    uint32_t prow0 = sb + (PS_OFF + (w * 16 + gid) * PSTR) * 4;
    uint32_t prow1 = prow0 + 8 * PSTR * 4;

    for (int kt = 0; kt < NN / 64; kt++) {
        int p = kt & 1;
        CP_WAIT1();
        __syncthreads();

        uint32_t ksb = sb + KS_OFF(p) * 4;
        uint32_t vsb = sb + VS_OFF(p) * 4;

        // --- S = Q @ K^T : 8 n-tiles x 4 k-steps ---
        float s[8][4];
        #pragma unroll
        for (int nt = 0; nt < 8; nt++)
            #pragma unroll
            for (int t = 0; t < 4; t++) s[nt][t] = 0.f;

        #pragma unroll
        for (int ks = 0; ks < 4; ks++) {
            #pragma unroll
            for (int nt = 0; nt < 8; nt++) {
                uint32_t addr = ksb + ((8 * nt + gid) * KSTR + 8 * ks + tg) * 4;
                uint32_t b0 = lds32(addr);
                uint32_t b1 = lds32(addr + 16);
                mma816(s[nt], qa[ks], b0, b1);
            }
        }

        // --- online softmax (rows gid and gid+8; quad = 4 lanes share a row) ---
        float mt0 = -3.0e38f, mt1 = -3.0e38f;
        #pragma unroll
        for (int nt = 0; nt < 8; nt++) {
            mt0 = fmaxf(mt0, fmaxf(s[nt][0], s[nt][1]));
            mt1 = fmaxf(mt1, fmaxf(s[nt][2], s[nt][3]));
        }
        mt0 = fmaxf(mt0, __shfl_xor_sync(0xffffffffu, mt0, 1));
        mt0 = fmaxf(mt0, __shfl_xor_sync(0xffffffffu, mt0, 2));
        mt1 = fmaxf(mt1, __shfl_xor_sync(0xffffffffu, mt1, 1));
        mt1 = fmaxf(mt1, __shfl_xor_sync(0xffffffffu, mt1, 2));

        float mn0 = fmaxf(m0, mt0), mn1 = fmaxf(m1, mt1);
        float al0 = __expf(m0 - mn0), al1 = __expf(m1 - mn1);
        m0 = mn0; m1 = mn1;

        float rs0 = 0.f, rs1 = 0.f;
        #pragma unroll
        for (int nt = 0; nt < 8; nt++) {
            float p0 = __expf(s[nt][0] - mn0);
            float p1 = __expf(s[nt][1] - mn0);
            float p2 = __expf(s[nt][2] - mn1);
            float p3 = __expf(s[nt][3] - mn1);
            rs0 += p0 + p1;
            rs1 += p2 + p3;
            uint32_t coff = (8 * nt + 2 * tg) * 4;
            sts64(prow0 + coff, f2tf32(p0), f2tf32(p1));
            sts64(prow1 + coff, f2tf32(p2), f2tf32(p3));
        }
        rs0 += __shfl_xor_sync(0xffffffffu, rs0, 1);
        rs0 += __shfl_xor_sync(0xffffffffu, rs0, 2);
        rs1 += __shfl_xor_sync(0xffffffffu, rs1, 1);
        rs1 += __shfl_xor_sync(0xffffffffu, rs1, 2);
        l0 = l0 * al0 + rs0;
        l1 = l1 * al1 + rs1;
        #pragma unroll
        for (int nt = 0; nt < 4; nt++) {
            acc[nt][0] *= al0; acc[nt][1] *= al0;
            acc[nt][2] *= al1; acc[nt][3] *= al1;
        }
        __syncwarp();  // P rows of this warp written by its own lanes only

        // --- O += P @ V : 4 n-tiles (32 hd cols) x 8 k-steps ---
        #pragma unroll
        for (int ks = 0; ks < 8; ks++) {
            uint32_t pad = prow0 + (8 * ks + tg) * 4;
            uint32_t pa[4];
            pa[0] = lds32(pad);
            pa[1] = lds32(pad + 8 * PSTR * 4);
            pa[2] = lds32(pad + 16);
            pa[3] = lds32(pad + 8 * PSTR * 4 + 16);
            #pragma unroll
            for (int nt = 0; nt < 4; nt++) {
                uint32_t vaddr = vsb + ((8 * ks + tg) * VSTR + 8 * nt + gid) * 4;
                uint32_t b0 = lds32(vaddr);
                uint32_t b1 = lds32(vaddr + 4 * VSTR * 4);
                mma816(acc[nt], pa, b0, b1);
            }
        }
        __syncthreads();  // everyone done with Ks/Vs[p] before overwrite

        // --- prefetch tile kt+2 into buffer p ---
        if (kt + 2 < NN / 64) {
            int k0 = (kt + 2) * 64;
            #pragma unroll
            for (int i = 0; i < 2; i++) {
                int e = tid + i * 256;
                int row = e >> 3, ch = e & 7;
                CP_ASYNC16(sb + (KS_OFF(p) + row * KSTR + ch * 4) * 4,
                           Kp + (size_t)(k0 + row) * DD + ch * 4);
                CP_ASYNC16(sb + (VS_OFF(p) + row * VSTR + ch * 4) * 4,
                           Vp + (size_t)(k0 + row) * DD + ch * 4);
            }
        }
        CP_COMMIT();
    }

    // --- epilogue ---
    float i0 = 1.0f / l0, i1 = 1.0f / l1;
    float* o0 = O + base + (size_t)(q0 + w * 16 + gid) * DD;
    float* o1 = o0 + (size_t)8 * DD;
    #pragma unroll
    for (int nt = 0; nt < 4; nt++) {
        int c = 8 * nt + 2 * tg;
        float2 r0 = make_float2(acc[nt][0] * i0, acc[nt][1] * i0);
        float2 r1 = make_float2(acc[nt][2] * i1, acc[nt][3] * i1);
        *(float2*)(o0 + c) = r0;
        *(float2*)(o1 + c) = r1;
    }
}

// ---------------------------------------------------------------------------
// Launch
// ---------------------------------------------------------------------------
extern "C" void kernel_launch(void* const* d_in, const int* in_sizes, int n_in,
                              void* d_out, int out_size) {
    const float* x1 = (const float*)d_in[0];
    const float* x2 = (const float*)d_in[1];
    const float* Wq = (const float*)d_in[2];
    const float* Wk = (const float*)d_in[3];
    const float* Wv = (const float*)d_in[4];
    const float* Wo = (const float*)d_in[5];
    const float* bq = (const float*)d_in[6];
    const float* bk = (const float*)d_in[7];
    const float* bv = (const float*)d_in[8];
    const float* bo = (const float*)d_in[9];
    float* out = (float*)d_out;

    float *x2f, *q, *k, *v, *att;
    cudaGetSymbolAddress((void**)&x2f, g_x2f);
    cudaGetSymbolAddress((void**)&q, g_q);
    cudaGetSymbolAddress((void**)&k, g_k);
    cudaGetSymbolAddress((void**)&v, g_v);
    cudaGetSymbolAddress((void**)&att, g_att);

    cudaFuncSetAttribute(flash_mma_kernel, cudaFuncAttributeMaxDynamicSharedMemorySize, SMEM_BYTES);

    // 1. neighborhood fuse
    neigh_fuse_kernel<<<BB * NN / 8, 256>>>(x2, x2f);

    // 2. Q/K/V projections (fp32)
    dim3 ggrid(BB * NN / 64, DD / 64);
    gemm_nt_bias<<<ggrid, 256>>>(x1, Wq, bq, q);
    gemm_nt_bias<<<ggrid, 256>>>(x2f, Wk, bk, k);
    gemm_nt_bias<<<ggrid, 256>>>(x2f, Wv, bv, v);

    // 3. tf32 mma.sync flash attention: 32 q-tiles x 16 (b,h)
    dim3 agrid(NN / 128, BB * NH);
    flash_mma_kernel<<<agrid, 256, SMEM_BYTES>>>(q, k, v, att);

    // 4. output projection -> d_out
    gemm_nt_bias<<<ggrid, 256>>>(att, Wo, bo, out);
}